// round 1
// baseline (speedup 1.0000x reference)
#include <cuda_runtime.h>
#include <math.h>

#define BB    8
#define RR    128
#define FM    19
#define FM2   (FM*FM)      // 361
#define PS    7
#define NPOS  49
#define C0    1024
#define C1    256
#define C2    256
#define C3    32
#define NSLOT (BB*RR)      // 1024
#define SMAXC 18

// output layout: er_c [B,1,R,4] | out_c [B,R,32,7,7] | keep_count [B]
#define OUT_ER   0
#define OUT_FEAT (NSLOT*4)                       // 4096
#define OUT_KEEP (OUT_FEAT + NSLOT*C3*NPOS)      // 4096 + 1605632

// ---------------- static device scratch (no allocs allowed) ----------------
__device__ int   g_keep[BB];
__device__ int   g_ybase[NSLOT*PS], g_ylen[NSLOT*PS];
__device__ int   g_xbase[NSLOT*PS], g_xlen[NSLOT*PS];
__device__ float g_ft[BB*FM2*C0];            // [b][y*19+x][c]   11.8 MB
__device__ float g_pooled[NSLOT*NPOS*C0];    // [slot][pos][c]   205 MB
__device__ float g_x1[NSLOT*NPOS*C1];        // [slot][pos][oc]   51 MB
__device__ float g_x2[NSLOT*NPOS*C2];        //                   51 MB
__device__ float g_W1t[C0*9*C1];             // [ic][k][oc]
__device__ float g_W2t[C1*9*C2];
__device__ float g_W3t[C2*C3];               // [ic][oc]

// ---------------- ROI decode + per-batch stable compaction -----------------
__global__ void k_setup(const float* __restrict__ roi, float* __restrict__ out) {
    int b = blockIdx.x, r = threadIdx.x;
    const float* p = roi + (size_t)(b*RR + r)*5;
    int rl[4], cc[4];
#pragma unroll
    for (int k = 0; k < 4; ++k) {
        float v = p[1+k] * 18.75f;         // * IMG/16 in fp32, exact as reference
        rl[k] = (int)v;                    // trunc toward zero == astype(int32)
        int c = rl[k] < 0 ? 0 : rl[k];
        cc[k] = c > SMAXC ? SMAXC : c;
    }
    int valid = (cc[2] > cc[0]) && (cc[3] > cc[1]);

    __shared__ int flags[RR];
    __shared__ int pre[RR];
    flags[r] = valid;
    __syncthreads();
    if (r == 0) {
        int run = 0;
        for (int i = 0; i < RR; ++i) { pre[i] = run; run += flags[i]; }
        g_keep[b] = run;
        out[OUT_KEEP + b] = (float)run;
    }
    __syncthreads();

    if (valid) {
        int slot = b*RR + pre[r];
#pragma unroll
        for (int k = 0; k < 4; ++k)
            out[OUT_ER + slot*4 + k] = (float)rl[k] * (16.0f/300.0f);
        int xmin = cc[0], ymin = cc[1], xmax = cc[2], ymax = cc[3];
        int Hy = ymax - ymin + 1, Hx = xmax - xmin + 1;
#pragma unroll
        for (int i = 0; i < PS; ++i) {
            int sy = (i*Hy)/PS,  ey = ((i+1)*Hy + PS - 1)/PS;
            g_ybase[slot*PS+i] = ymin + sy;  g_ylen[slot*PS+i] = ey - sy;
            int sx = (i*Hx)/PS,  ex = ((i+1)*Hx + PS - 1)/PS;
            g_xbase[slot*PS+i] = xmin + sx;  g_xlen[slot*PS+i] = ex - sx;
        }
    }
}

// ---------------- features [b][c][y][x] -> [b][yx][c] (tiled) ---------------
__global__ void k_ftrans(const float* __restrict__ f) {
    __shared__ float t[32][33];
    int b  = blockIdx.z;
    int yx0 = blockIdx.x*32, c0 = blockIdx.y*32;
    int tx = threadIdx.x, ty = threadIdx.y;
    int yx = yx0 + tx, c = c0 + ty;
    if (yx < FM2) t[ty][tx] = f[((size_t)b*C0 + c)*FM2 + yx];
    __syncthreads();
    int c2 = c0 + tx, yx2 = yx0 + ty;
    if (yx2 < FM2) g_ft[((size_t)b*FM2 + yx2)*C0 + c2] = t[tx][ty];
}

// ---------------- weight transposes: [oc][ic][3][3] -> [ic][k][oc] ----------
__global__ void k_w1t(const float* __restrict__ w) {
    int ick = blockIdx.x, oc = threadIdx.x;
    int ic = ick/9, k = ick - ic*9;
    g_W1t[(size_t)ick*C1 + oc] = w[((size_t)oc*C0 + ic)*9 + k];
}
__global__ void k_w2t(const float* __restrict__ w) {
    int ick = blockIdx.x, oc = threadIdx.x;
    int ic = ick/9, k = ick - ic*9;
    g_W2t[(size_t)ick*C2 + oc] = w[((size_t)oc*C1 + ic)*9 + k];
}
__global__ void k_w3t(const float* __restrict__ w) {
    int oc = blockIdx.x, ic = threadIdx.x;    // <<<32,256>>>
    g_W3t[ic*C3 + oc] = w[oc*C2 + ic];
}

// ---------------- adaptive pooling on valid slots only ----------------------
__global__ void k_pool() {
    int b = blockIdx.z, j = blockIdx.y;
    if (j >= g_keep[b]) return;
    int slot = b*RR + j;
    int c = blockIdx.x*128 + threadIdx.x;

    __shared__ int yb[PS], yl[PS], xb[PS], xl[PS];
    if (threadIdx.x < PS) {
        int i = threadIdx.x;
        yb[i] = g_ybase[slot*PS+i]; yl[i] = g_ylen[slot*PS+i];
        xb[i] = g_xbase[slot*PS+i]; xl[i] = g_xlen[slot*PS+i];
    }
    __syncthreads();

    const float* fb = g_ft + (size_t)b*FM2*C0 + c;
    float* op = g_pooled + (size_t)slot*NPOS*C0 + c;
#pragma unroll
    for (int p = 0; p < PS; ++p) {
        int y0 = yb[p], ny = yl[p];
        float ry = 1.0f/(float)ny;
#pragma unroll
        for (int q = 0; q < PS; ++q) {
            int x0 = xb[q], nx = xl[q];
            float s = 0.f;
            for (int dy = 0; dy < ny; ++dy) {
                const float* row = fb + ((size_t)((y0+dy)*FM + x0))*C0;
                for (int dx = 0; dx < nx; ++dx) s += row[(size_t)dx*C0];
            }
            op[(size_t)(p*PS + q)*C0] = s * ry * (1.0f/(float)nx);
        }
    }
}

// ---------------- 3x3 conv + BN + ReLU, CTA=slot, thread=oc -----------------
// STAGE 1: g_pooled(IC=1024) -> g_x1 ; STAGE 2: g_x1(IC=256) -> g_x2
template<int STAGE>
__global__ void __launch_bounds__(256, 2) k_conv3x3(
    const float* __restrict__ bias, const float* __restrict__ gg,
    const float* __restrict__ be,   const float* __restrict__ mm,
    const float* __restrict__ vv)
{
    constexpr int IC = (STAGE == 1) ? C0 : C1;
    int b = blockIdx.x >> 7, j = blockIdx.x & 127;
    if (j >= g_keep[b]) return;
    int slot = blockIdx.x;

    const float* in  = (STAGE == 1) ? (const float*)g_pooled : (const float*)g_x1;
    const float* wt  = (STAGE == 1) ? (const float*)g_W1t    : (const float*)g_W2t;
    float*       outb= (STAGE == 1) ? (float*)g_x1           : (float*)g_x2;

    __shared__ __align__(16) float sin[64*108];   // [ic][9 rows][12 cols] zero-padded
    for (int i = threadIdx.x; i < 64*108; i += 256) sin[i] = 0.f;
    __syncthreads();

    int oc = threadIdx.x;
    float acc[NPOS];
#pragma unroll
    for (int i = 0; i < NPOS; ++i) acc[i] = 0.f;

    const float* inp = in + (size_t)slot*NPOS*IC;

#pragma unroll 1
    for (int ch = 0; ch < IC/64; ++ch) {
        // stage input chunk into padded smem (coalesced over ic)
        for (int idx = threadIdx.x; idx < 64*NPOS; idx += 256) {
            int icl = idx & 63, pos = idx >> 6;
            int py = pos/7, px = pos - py*7;
            sin[icl*108 + (py+1)*12 + (px+1)] = inp[(size_t)pos*IC + ch*64 + icl];
        }
        __syncthreads();

        const float* wp = wt + ((size_t)(ch*64)*9)*256 + oc;
        float w[9];
#pragma unroll
        for (int k = 0; k < 9; ++k) w[k] = wp[k*256];

#pragma unroll 1
        for (int ic = 0; ic < 64; ++ic) {
            // prefetch next ic's weights (hides L2 latency behind the 441 FMAs)
            float wn[9];
            {
                int icn = (ic + 1 < 64) ? ic + 1 : 63;
                const float* wq = wt + ((size_t)(ch*64 + icn)*9)*256 + oc;
#pragma unroll
                for (int k = 0; k < 9; ++k) wn[k] = wq[k*256];
            }
            const float4* rp = (const float4*)(sin + ic*108);
#pragma unroll
            for (int R = 0; R < 9; ++R) {   // smem row R == input row R-1
                float4 f0 = rp[R*3+0], f1 = rp[R*3+1], f2 = rp[R*3+2];
                float r[12] = {f0.x,f0.y,f0.z,f0.w, f1.x,f1.y,f1.z,f1.w,
                               f2.x,f2.y,f2.z,f2.w};
                int prlo = (R-2 < 0) ? 0 : R-2;
                int prhi = (R > 6) ? 6 : R;
#pragma unroll
                for (int pr = prlo; pr <= prhi; ++pr) {
                    int ky = R - pr;
#pragma unroll
                    for (int px = 0; px < 7; ++px) {
                        float a = acc[pr*7 + px];
                        a = fmaf(w[ky*3+0], r[px+0], a);
                        a = fmaf(w[ky*3+1], r[px+1], a);
                        a = fmaf(w[ky*3+2], r[px+2], a);
                        acc[pr*7 + px] = a;
                    }
                }
            }
#pragma unroll
            for (int k = 0; k < 9; ++k) w[k] = wn[k];
        }
        __syncthreads();
    }

    // fused bias + BN + ReLU epilogue
    float sc = gg[oc] * rsqrtf(vv[oc] + 1e-5f);
    float sh = bias[oc]*sc + be[oc] - mm[oc]*sc;
    float* op = outb + (size_t)slot*NPOS*256 + oc;
#pragma unroll
    for (int p = 0; p < NPOS; ++p) {
        float val = fmaf(acc[p], sc, sh);
        op[(size_t)p*256] = val > 0.f ? val : 0.f;
    }
}

// ---------------- 1x1 conv + BN + ReLU -> final output ----------------------
__global__ void k_conv1x1(const float* __restrict__ gg, const float* __restrict__ be,
                          const float* __restrict__ mm, const float* __restrict__ vv,
                          float* __restrict__ out)
{
    int b = blockIdx.x >> 7, j = blockIdx.x & 127;
    if (j >= g_keep[b]) return;
    int slot = blockIdx.x;

    __shared__ float sw[C2*C3];
    for (int i = threadIdx.x; i < C2*C3; i += 256) sw[i] = g_W3t[i];
    __syncthreads();

    const float* xp = g_x2 + (size_t)slot*NPOS*C2;
    for (int idx = threadIdx.x; idx < NPOS*C3; idx += 256) {
        int oc = idx & 31, pos = idx >> 5;     // whole warp shares pos -> broadcast loads
        const float* xr = xp + (size_t)pos*C2;
        float acc = 0.f;
#pragma unroll 8
        for (int ic = 0; ic < C2; ++ic) acc = fmaf(xr[ic], sw[ic*C3 + oc], acc);
        float sc = gg[oc] * rsqrtf(vv[oc] + 1e-5f);
        float sh = be[oc] - mm[oc]*sc;         // conv3 has no bias
        float val = fmaf(acc, sc, sh);
        out[OUT_FEAT + ((size_t)slot*C3 + oc)*NPOS + pos] = val > 0.f ? val : 0.f;
    }
}

// ---------------------------------------------------------------------------
extern "C" void kernel_launch(void* const* d_in, const int* in_sizes, int n_in,
                              void* d_out, int out_size) {
    const float* roi  = (const float*)d_in[0];
    const float* feat = (const float*)d_in[1];
    const float* W1   = (const float*)d_in[2];
    const float* b1   = (const float*)d_in[3];
    const float* g1   = (const float*)d_in[4];
    const float* be1  = (const float*)d_in[5];
    const float* m1   = (const float*)d_in[6];
    const float* v1   = (const float*)d_in[7];
    const float* W2   = (const float*)d_in[8];
    const float* b2   = (const float*)d_in[9];
    const float* g2   = (const float*)d_in[10];
    const float* be2  = (const float*)d_in[11];
    const float* m2   = (const float*)d_in[12];
    const float* v2   = (const float*)d_in[13];
    const float* W3   = (const float*)d_in[14];
    const float* g3   = (const float*)d_in[15];
    const float* be3  = (const float*)d_in[16];
    const float* m3   = (const float*)d_in[17];
    const float* v3   = (const float*)d_in[18];
    float* out = (float*)d_out;

    // invalid ROI slots (er, out_c tail) must be exactly zero
    cudaMemsetAsync(d_out, 0, (size_t)out_size * sizeof(float));

    k_setup<<<BB, RR>>>(roi, out);
    k_ftrans<<<dim3(12, 32, BB), dim3(32, 32)>>>(feat);
    k_w1t<<<C0*9, C1>>>(W1);
    k_w2t<<<C1*9, C2>>>(W2);
    k_w3t<<<C3, C2>>>(W3);

    k_pool<<<dim3(8, RR, BB), 128>>>();
    k_conv3x3<1><<<NSLOT, 256>>>(b1, g1, be1, m1, v1);
    k_conv3x3<2><<<NSLOT, 256>>>(b2, g2, be2, m2, v2);
    k_conv1x1<<<NSLOT, 256>>>(g3, be3, m3, v3, out);
}